// round 5
// baseline (speedup 1.0000x reference)
#include <cuda_runtime.h>
#include <cuda_fp16.h>
#include <cstdint>

#define V     32000
#define BB    8
#define SS    512
#define RR    32
#define BM    64
#define ROWS  (BB*SS)
#define CAP   1024
#define NWORK 136
#define GRID  (BB + NWORK)
#define NTOPK (8 + ROWS)              /* first 8 items are num items */
#define NTRANS (BB*(SS-1))

// ---------------- device scratch (allocation-free rule) ----------------
__device__ int    d_beam_idx[ROWS*BM];
__device__ float  d_w[ROWS*BM];                 // exp(em - em_ref)
__device__ float  d_emref[ROWS];
__device__ __half d_dt[(size_t)NTRANS*BM*BM];   // 33.5 MB expm1(trans)
__device__ float  d_num[BB], d_den[BB];
__device__ int    d_i64flag;
__device__ int    d_rowflag[ROWS];
__device__ int    d_tileflag[BB*SS];
__device__ int    g_topk_head, g_trans_head, g_rows_done;

// ---------------- helpers ----------------
__device__ __forceinline__ int get_tgt(const void* __restrict__ tg, int row){
    if (d_i64flag) return (int)((const long long*)tg)[row];
    return ((const int*)tg)[row];
}
__device__ __forceinline__ uint32_t f2k(float f){
    uint32_t u = __float_as_uint(f);
    return (u & 0x80000000u) ? ~u : (u | 0x80000000u);
}
__device__ __forceinline__ float k2f(uint32_t k){
    uint32_t u = (k & 0x80000000u) ? (k ^ 0x80000000u) : ~k;
    return __uint_as_float(u);
}
__device__ __forceinline__ void spin_acq(const int* f){
    volatile const int* vf = (volatile const int*)f;
    while (*vf == 0) __nanosleep(64);
    __threadfence();
}
__device__ __forceinline__ unsigned long long pk2(float a, float b){
    unsigned long long r; asm("mov.b64 %0,{%1,%2};" : "=l"(r) : "f"(a), "f"(b)); return r;
}
__device__ __forceinline__ unsigned long long fma2_(unsigned long long a,
        unsigned long long b, unsigned long long c){
    unsigned long long d;
    asm("fma.rn.f32x2 %0,%1,%2,%3;" : "=l"(d) : "l"(a), "l"(b), "l"(c));
    return d;
}
__device__ __forceinline__ float2 up2(unsigned long long p){
    float2 f; asm("mov.b64 {%0,%1},%2;" : "=f"(f.x), "=f"(f.y) : "l"(p)); return f;
}

// ---------------- shared memory union (16B-aligned: cp.async.cg 16B needs it) --
union alignas(16) SmemU {
    struct { unsigned long long cand[CAP]; } tk;                       // 8 KB
    struct { float e1t[RR][BM]; float e2t[RR][BM]; } tr;               // 16 KB
    struct { __align__(16) __half dring[4][4096];
             __align__(16) float  wring[4][BM];
             float spr[BM]; float part[4][BM]; float rhist[SS]; } sc;  // 37 KB
};

// ---------------- init (reset flags/counters each replay) ----------------
__global__ void init_kernel(){
    int i = blockIdx.x*blockDim.x + threadIdx.x;
    if (i < ROWS)   d_rowflag[i]  = 0;
    if (i < BB*SS)  d_tileflag[i] = 0;
    if (i == 0) { g_topk_head = 0; g_trans_head = 0; g_rows_done = 0; }
}

__global__ void detect_kernel(const int* __restrict__ tg32){
    __shared__ int s_or;
    if (threadIdx.x == 0) s_or = 0;
    __syncthreads();
    int acc = 0;
    for (int i = threadIdx.x; i < ROWS/2; i += 256) acc |= tg32[2*i + 1];
    atomicOr(&s_or, acc);
    __syncthreads();
    if (threadIdx.x == 0) d_i64flag = (s_or == 0) ? 1 : 0;
}

// ============================================================================
// work items
// ============================================================================
__device__ void num_item(const float* __restrict__ em, const void* __restrict__ tg,
                         const float* __restrict__ E1, const float* __restrict__ E2, int b)
{
    __shared__ float nred[8];
    const int tid = threadIdx.x;
    float v = 0.f;
    for (int t = tid; t < SS; t += 256) {
        const int row = b*SS + t;
        const int cur = get_tgt(tg, row);
        float x = em[(size_t)row*V + cur];
        if (t > 0) {
            const int pv = get_tgt(tg, row-1);
            const float4* e1 = (const float4*)(E1 + (size_t)pv*RR);
            const float4* e2 = (const float4*)(E2 + (size_t)cur*RR);
            float d = 0.f;
            #pragma unroll
            for (int q = 0; q < 8; q++) {
                float4 a = e1[q], c = e2[q];
                d += a.x*c.x + a.y*c.y + a.z*c.z + a.w*c.w;
            }
            x += d;
        }
        v += x;
    }
    #pragma unroll
    for (int o = 16; o; o >>= 1) v += __shfl_xor_sync(0xffffffffu, v, o);
    if ((tid & 31) == 0) nred[tid >> 5] = v;
    __syncthreads();
    if (tid == 0) {
        float s = 0.f;
        for (int i = 0; i < 8; i++) s += nred[i];
        d_num[b] = s;
    }
}

__device__ void topk_item(const float* __restrict__ em, const void* __restrict__ tgt,
                          int row, SmemU& U)
{
    __shared__ int s_cnt, s_has;
    __shared__ unsigned long long s_pack;
    __shared__ int      sel_idx[BM];
    __shared__ uint32_t sel_key[BM];
    __shared__ float    val[BM];

    const int tid = threadIdx.x;
    const float4* rp = (const float4*)(em + (size_t)row * V);
    const uint32_t THR = f2k(2.5f);

    if (tid == 0) { s_cnt = 0; s_has = 0; }
    __syncthreads();

    // single HBM pass, MLP=8 (8 outstanding LDG.128 per thread)
    for (int base = 0; base < V/4; base += 2048) {
        float4 v[8];
        #pragma unroll
        for (int u = 0; u < 8; u++) {
            int idx = base + tid + u*256;
            if (idx < V/4) v[u] = rp[idx];
            else v[u] = make_float4(-1e30f,-1e30f,-1e30f,-1e30f);
        }
        #pragma unroll
        for (int u = 0; u < 8; u++) {
            int i4 = base + tid + u*256;
            float f[4] = {v[u].x, v[u].y, v[u].z, v[u].w};
            #pragma unroll
            for (int c = 0; c < 4; c++) {
                uint32_t k = f2k(f[c]);
                if (k > THR) {
                    int p = atomicAdd(&s_cnt, 1);
                    if (p < CAP)
                        U.tk.cand[p] = ((unsigned long long)k << 32) | (uint32_t)(~(4*i4 + c));
                }
            }
        }
    }
    __syncthreads();
    const int cnt = s_cnt;

    if (cnt >= BM && cnt <= CAP) {
        for (int ci = tid; ci < cnt; ci += 256) {
            unsigned long long e = U.tk.cand[ci];
            int rank = 0;
            for (int cj = 0; cj < cnt; cj++) rank += (U.tk.cand[cj] > e);
            if (rank < BM) {
                sel_key[rank] = (uint32_t)(e >> 32);
                sel_idx[rank] = (int)(~(uint32_t)e);
            }
        }
    } else {
        // exact fallback (never on bench data): 64 rounds of max extraction
        unsigned long long last = ~0ull;
        for (int r = 0; r < BM; r++) {
            if (tid == 0) s_pack = 0ull;
            __syncthreads();
            unsigned long long lm = 0ull;
            for (int i = tid; i < V; i += 256) {
                uint32_t k = f2k(em[(size_t)row*V + i]);
                unsigned long long pk = ((unsigned long long)k << 32) | (uint32_t)(~i);
                if (pk < last && pk > lm) lm = pk;
            }
            atomicMax(&s_pack, lm);
            __syncthreads();
            if (tid == 0) {
                sel_key[r] = (uint32_t)(s_pack >> 32);
                sel_idx[r] = (int)(~(uint32_t)s_pack);
            }
            __syncthreads();
            last = s_pack;
            __syncthreads();
        }
    }
    __syncthreads();

    // force target into beam (drop min-value / max-index element)
    const int tg = get_tgt(tgt, row);
    if (tid < BM && sel_idx[tid] == tg) s_has = 1;
    __syncthreads();
    if (!s_has) {
        if (tid == 0) s_pack = ~0ull;
        __syncthreads();
        unsigned long long my = ~0ull;
        if (tid < BM) {
            my = ((unsigned long long)sel_key[tid] << 32) | (uint32_t)(~sel_idx[tid]);
            atomicMin(&s_pack, my);
        }
        __syncthreads();
        if (tid < BM && my == s_pack) {
            sel_idx[tid] = tg;
            sel_key[tid] = f2k(em[(size_t)row*V + tg]);
        }
    }
    __syncthreads();

    if (tid < BM) {
        val[tid] = k2f(sel_key[tid]);
        d_beam_idx[row*BM + tid] = sel_idx[tid];
    }
    __syncthreads();
    if (tid < BM) {
        float er = val[0];
        d_w[(size_t)row*BM + tid] = __expf(val[tid] - er);
        if (tid == 0) d_emref[row] = er;
    }
    __syncthreads();
    __threadfence();
    if (tid == 0) {
        *(volatile int*)&d_rowflag[row] = 1;
        atomicAdd(&g_rows_done, 1);
    }
}

__device__ void trans_item(const float* __restrict__ E1, const float* __restrict__ E2,
                           int it, SmemU& U)
{
    const int tid = threadIdx.x;
    const int t = 1 + (it >> 3), b = it & 7;
    const int rowp = b*SS + t - 1, rowc = rowp + 1;

    if (tid == 0) spin_acq(&d_rowflag[rowp]);
    if (tid == 1) spin_acq(&d_rowflag[rowc]);
    __syncthreads();

    for (int i = tid; i < BM*8; i += 256) {
        int j = i >> 3, q = i & 7;
        float4 v = ((const float4*)(E1 + (size_t)d_beam_idx[rowp*BM + j]*RR))[q];
        U.tr.e1t[q*4+0][j] = v.x; U.tr.e1t[q*4+1][j] = v.y;
        U.tr.e1t[q*4+2][j] = v.z; U.tr.e1t[q*4+3][j] = v.w;
        float4 u = ((const float4*)(E2 + (size_t)d_beam_idx[rowc*BM + j]*RR))[q];
        U.tr.e2t[q*4+0][j] = u.x; U.tr.e2t[q*4+1][j] = u.y;
        U.tr.e2t[q*4+2][j] = u.z; U.tr.e2t[q*4+3][j] = u.w;
    }
    __syncthreads();

    const int tj = tid >> 4, tk = tid & 15, j0 = tj*4, k0 = tk*4;
    unsigned long long acc[4][2];
    #pragma unroll
    for (int a = 0; a < 4; a++) { acc[a][0] = 0ull; acc[a][1] = 0ull; }
    #pragma unroll
    for (int r = 0; r < RR; r++) {
        float4 A  = *(const float4*)&U.tr.e1t[r][j0];
        float4 Bv = *(const float4*)&U.tr.e2t[r][k0];
        unsigned long long b01 = pk2(Bv.x, Bv.y), b23 = pk2(Bv.z, Bv.w);
        unsigned long long a0 = pk2(A.x, A.x), a1 = pk2(A.y, A.y);
        unsigned long long a2 = pk2(A.z, A.z), a3 = pk2(A.w, A.w);
        acc[0][0] = fma2_(a0, b01, acc[0][0]); acc[0][1] = fma2_(a0, b23, acc[0][1]);
        acc[1][0] = fma2_(a1, b01, acc[1][0]); acc[1][1] = fma2_(a1, b23, acc[1][1]);
        acc[2][0] = fma2_(a2, b01, acc[2][0]); acc[2][1] = fma2_(a2, b23, acc[2][1]);
        acc[3][0] = fma2_(a3, b01, acc[3][0]); acc[3][1] = fma2_(a3, b23, acc[3][1]);
    }

    __half* outp = d_dt + (size_t)it * BM * BM;
    #pragma unroll
    for (int jj = 0; jj < 4; jj++) {
        float2 p0 = up2(acc[jj][0]), p1 = up2(acc[jj][1]);
        float dv[4] = {p0.x, p0.y, p1.x, p1.y};
        #pragma unroll
        for (int c = 0; c < 4; c++) {       // expm1: t + t^2/2 + t^3/6
            float x = dv[c];
            dv[c] = x * fmaf(x, fmaf(x, 0.166666667f, 0.5f), 1.0f);
        }
        *(__half2*)(outp + (j0+jj)*BM + k0    ) = __floats2half2_rn(dv[0], dv[1]);
        *(__half2*)(outp + (j0+jj)*BM + k0 + 2) = __floats2half2_rn(dv[2], dv[3]);
    }
    __syncthreads();
    __threadfence();
    if (tid == 0) *(volatile int*)&d_tileflag[b*SS + t] = 1;
}

// ============================================================================
// scan CTA (one per batch)
// ============================================================================
__device__ __forceinline__ void sc_prefetch(int b, int t, SmemU& U)
{
    const int st = (t-1) & 3;
    const __half* src = d_dt + (size_t)((t-1)*8 + b) * BM * BM;   // it = (t-1)*8+b
    uint32_t ds = (uint32_t)__cvta_generic_to_shared(&U.sc.dring[st][0]);
    #pragma unroll
    for (int i = threadIdx.x; i < 512; i += 256)
        asm volatile("cp.async.cg.shared.global [%0],[%1],16;\n"
                     :: "r"(ds + i*16), "l"(src + i*8));
    if (threadIdx.x < 16) {
        const float* ws = d_w + (size_t)(b*SS + t) * BM;
        uint32_t dw = (uint32_t)__cvta_generic_to_shared(&U.sc.wring[st][0]);
        asm volatile("cp.async.cg.shared.global [%0],[%1],16;\n"
                     :: "r"(dw + threadIdx.x*16), "l"(ws + threadIdx.x*4));
    }
}

__device__ void scan_cta(int b, SmemU& U)
{
    __shared__ float s_r, rbuf[4];
    const int tid = threadIdx.x;
    const int w = tid >> 5, l = tid & 31;

    for (int t = 1; t <= 4; t++) {
        spin_acq(&d_tileflag[b*SS + t]);
        sc_prefetch(b, t, U);
        asm volatile("cp.async.commit_group;\n");
    }
    // tile(b,1) flag implies topk row (b,0) done -> w row 0 readable
    if (tid < BM) U.sc.spr[tid] = d_w[(size_t)(b*SS)*BM + tid];
    if (tid == 0) s_r = 1.0f;
    __syncthreads();

    for (int t = 1; t < SS; t++) {
        asm volatile("cp.async.wait_group 3;\n");
        __syncthreads();

        const int st = (t-1) & 3;
        const float r = s_r;
        if (tid < 128) {
            const int j0 = w * 16;
            float a0 = 0.f, a1 = 0.f, aS = 0.f;
            #pragma unroll
            for (int j = 0; j < 16; j++) {
                float q = U.sc.spr[j0 + j] * r;
                __half2 hv = *reinterpret_cast<const __half2*>(
                                  &U.sc.dring[st][(j0 + j)*BM + 2*l]);
                float2 df = __half22float2(hv);
                a0 = fmaf(q, df.x, a0);
                a1 = fmaf(q, df.y, a1);
                aS += q;
            }
            U.sc.part[w][2*l]   = a0 + aS;
            U.sc.part[w][2*l+1] = a1 + aS;
        }
        __syncthreads();

        if (tid < BM) {
            float acc = (U.sc.part[0][tid] + U.sc.part[1][tid])
                      + (U.sc.part[2][tid] + U.sc.part[3][tid]);
            float pv  = acc * U.sc.wring[st][tid];
            U.sc.spr[tid] = pv;
            if (tid == 0) s_r = __fdividef(1.0f, pv);
        }
        if (tid == 64) U.sc.rhist[t] = r;
        if (t + 4 < SS) {
            spin_acq(&d_tileflag[b*SS + t + 4]);
            sc_prefetch(b, t + 4, U);
        }
        asm volatile("cp.async.commit_group;\n");
    }
    __syncthreads();

    // den = M + sum(-log r) + log(sum spr) ; all topk rows of b done by now
    float v = (tid < BM) ? U.sc.spr[tid] : 0.f;
    if (tid < 128) {
        #pragma unroll
        for (int o = 16; o; o >>= 1) v += __shfl_xor_sync(0xffffffffu, v, o);
        if (l == 0) rbuf[w] = v;
    }
    __syncthreads();
    const float S = (rbuf[0] + rbuf[1]) + (rbuf[2] + rbuf[3]);
    __syncthreads();

    float lc = 0.f;
    if (tid < 128) {
        for (int t = 1 + tid; t < SS; t += 128) lc -= logf(U.sc.rhist[t]);
        #pragma unroll
        for (int o = 16; o; o >>= 1) lc += __shfl_xor_sync(0xffffffffu, lc, o);
        if (l == 0) rbuf[w] = lc;
    }
    __syncthreads();
    const float LC = (rbuf[0] + rbuf[1]) + (rbuf[2] + rbuf[3]);
    __syncthreads();

    float mv = 0.f;
    if (tid < 128) {
        for (int t = tid; t < SS; t += 128) mv += d_emref[b*SS + t];
        #pragma unroll
        for (int o = 16; o; o >>= 1) mv += __shfl_xor_sync(0xffffffffu, mv, o);
        if (l == 0) rbuf[w] = mv;
    }
    __syncthreads();
    const float M = (rbuf[0] + rbuf[1]) + (rbuf[2] + rbuf[3]);

    if (tid == 0) d_den[b] = M + LC + logf(S);
}

// ============================================================================
// fused persistent kernel
// ============================================================================
__global__ void __launch_bounds__(256) fused_kernel(
    const float* __restrict__ em, const void* __restrict__ tg,
    const float* __restrict__ E1, const float* __restrict__ E2)
{
    __shared__ __align__(16) SmemU U;
    __shared__ int s_it, s_kind;

    if (blockIdx.x < BB) { scan_cta(blockIdx.x, U); return; }

    bool tkx = false, trx = false;     // meaningful on tid 0 only
    while (true) {
        __syncthreads();               // protect smem union reuse
        if (threadIdx.x == 0) {
            int kind = 0, it = -1;
            if (!trx) {
                int th = *(volatile int*)&g_trans_head;
                if (th >= NTRANS) trx = true;
                else {
                    int t  = 1 + (th >> 3);
                    int rd = *(volatile int*)&g_rows_done;
                    if (tkx || rd >= 8*(t+1) + 48) {
                        it = atomicAdd(&g_trans_head, 1);
                        if (it < NTRANS) kind = 2; else { trx = true; it = -1; }
                    }
                }
            }
            if (kind == 0 && !tkx) {
                it = atomicAdd(&g_topk_head, 1);
                if (it < NTOPK) kind = 1; else { tkx = true; it = -1; }
            }
            if (kind == 0 && !trx) {
                it = atomicAdd(&g_trans_head, 1);
                if (it < NTRANS) kind = 2; else { trx = true; it = -1; }
            }
            s_kind = kind; s_it = it;
        }
        __syncthreads();
        const int kind = s_kind, it = s_it;
        if (kind == 0) break;
        if (kind == 1) {
            if (it < 8) num_item(em, tg, E1, E2, it);
            else {
                const int idx = it - 8;                 // t-major ordering
                const int t = idx >> 3, b = idx & 7;
                topk_item(em, tg, b*SS + t, U);
            }
        } else {
            trans_item(E1, E2, it, U);
        }
    }
}

// ============================================================================
// epilogue
// ============================================================================
__global__ void out_kernel(float* __restrict__ out, int out_size)
{
    __shared__ float ll[BB];
    const int t = threadIdx.x;
    if (t < BB) ll[t] = d_num[t] - d_den[t];
    __syncthreads();
    if (t == 0) {
        float sum = 0.f;
        for (int i = 0; i < BB; i++) sum += ll[i];
        if (out_size > BB) {
            out[0] = sum;
            for (int i = 0; i < BB; i++) out[1+i] = ll[i];
        } else if (out_size == BB) {
            for (int i = 0; i < BB; i++) out[i] = ll[i];
        } else {
            out[0] = sum;
        }
    }
}

// ============================================================================
extern "C" void kernel_launch(void* const* d_in, const int* in_sizes, int n_in,
                              void* d_out, int out_size)
{
    const float* em = (const float*)d_in[0];
    const void*  tg = d_in[1];
    const float* E1 = (const float*)d_in[3];
    const float* E2 = (const float*)d_in[4];
    float* out = (float*)d_out;

    init_kernel<<<(ROWS + 255)/256, 256>>>();
    detect_kernel<<<1, 256>>>((const int*)tg);
    fused_kernel<<<GRID, 256>>>(em, tg, E1, E2);
    out_kernel<<<1, 32>>>(out, out_size);
}

// round 6
// speedup vs baseline: 2.0004x; 2.0004x over previous
#include <cuda_runtime.h>
#include <cuda_fp16.h>
#include <cstdint>

#define V     32000
#define BB    8
#define SS    512
#define RR    32
#define BM    64
#define ROWS  (BB*SS)
#define CAP   1024
#define NTRANS (BB*(SS-1))
#define NPAIR 255               /* pairs (t=1,2),(3,4)..(509,510); leftover t=511 */

// ---------------- device scratch (allocation-free rule) ----------------
__device__ int    d_beam_idx[ROWS*BM];
__device__ float  d_w[ROWS*BM];                     // exp(em - em_ref)
__device__ float  d_emref[ROWS];
__device__ __half d_dt[(size_t)NTRANS*BM*BM];       // 33.5 MB expm1(trans)
__device__ __half d_c2[(size_t)BB*NPAIR*BM*BM];     // 16.7 MB pair-composed mats
__device__ float  d_num[BB], d_den[BB];
__device__ int    d_i64flag;

// ---------------- helpers ----------------
__device__ __forceinline__ int get_tgt(const void* __restrict__ tg, int row){
    if (d_i64flag) return (int)((const long long*)tg)[row];
    return ((const int*)tg)[row];
}
__device__ __forceinline__ uint32_t f2k(float f){
    uint32_t u = __float_as_uint(f);
    return (u & 0x80000000u) ? ~u : (u | 0x80000000u);
}
__device__ __forceinline__ float k2f(uint32_t k){
    uint32_t u = (k & 0x80000000u) ? (k ^ 0x80000000u) : ~k;
    return __uint_as_float(u);
}
__device__ __forceinline__ unsigned long long pk2(float a, float b){
    unsigned long long r; asm("mov.b64 %0,{%1,%2};" : "=l"(r) : "f"(a), "f"(b)); return r;
}
__device__ __forceinline__ unsigned long long fma2_(unsigned long long a,
        unsigned long long b, unsigned long long c){
    unsigned long long d;
    asm("fma.rn.f32x2 %0,%1,%2,%3;" : "=l"(d) : "l"(a), "l"(b), "l"(c));
    return d;
}
__device__ __forceinline__ float2 up2(unsigned long long p){
    float2 f; asm("mov.b64 {%0,%1},%2;" : "=f"(f.x), "=f"(f.y) : "l"(p)); return f;
}

__global__ void detect_kernel(const int* __restrict__ tg32){
    __shared__ int s_or;
    if (threadIdx.x == 0) s_or = 0;
    __syncthreads();
    int acc = 0;
    for (int i = threadIdx.x; i < ROWS/2; i += 256) acc |= tg32[2*i + 1];
    atomicOr(&s_or, acc);
    __syncthreads();
    if (threadIdx.x == 0) d_i64flag = (s_or == 0) ? 1 : 0;
}

// ============================================================================
// K1: exact top-64 per row via threshold candidate collection (R3-proven).
// ============================================================================
__global__ void __launch_bounds__(256) topk_kernel(
    const float* __restrict__ em, const void* __restrict__ tgt)
{
    __shared__ unsigned long long cand[CAP];
    __shared__ int s_cnt, s_has;
    __shared__ unsigned long long s_pack;
    __shared__ int      sel_idx[BM];
    __shared__ uint32_t sel_key[BM];
    __shared__ float    val[BM];

    const int tid = threadIdx.x, row = blockIdx.x;
    const float4* rp = (const float4*)(em + (size_t)row * V);
    const uint32_t THR = f2k(2.5f);

    if (tid == 0) { s_cnt = 0; s_has = 0; }
    __syncthreads();

    #pragma unroll 4
    for (int i = tid; i < V/4; i += 256) {
        float4 v = rp[i];
        float f[4] = {v.x, v.y, v.z, v.w};
        #pragma unroll
        for (int c = 0; c < 4; c++) {
            uint32_t k = f2k(f[c]);
            if (k > THR) {
                int p = atomicAdd(&s_cnt, 1);
                if (p < CAP)
                    cand[p] = ((unsigned long long)k << 32) | (uint32_t)(~(4*i + c));
            }
        }
    }
    __syncthreads();
    const int cnt = s_cnt;

    if (cnt >= BM && cnt <= CAP) {
        for (int ci = tid; ci < cnt; ci += 256) {
            unsigned long long e = cand[ci];
            int rank = 0;
            for (int cj = 0; cj < cnt; cj++) rank += (cand[cj] > e);
            if (rank < BM) {
                sel_key[rank] = (uint32_t)(e >> 32);
                sel_idx[rank] = (int)(~(uint32_t)e);
            }
        }
    } else {
        // exact fallback (never on bench data)
        unsigned long long last = ~0ull;
        for (int r = 0; r < BM; r++) {
            if (tid == 0) s_pack = 0ull;
            __syncthreads();
            unsigned long long lm = 0ull;
            for (int i = tid; i < V; i += 256) {
                uint32_t k = f2k(em[(size_t)row*V + i]);
                unsigned long long pk = ((unsigned long long)k << 32) | (uint32_t)(~i);
                if (pk < last && pk > lm) lm = pk;
            }
            atomicMax(&s_pack, lm);
            __syncthreads();
            if (tid == 0) {
                sel_key[r] = (uint32_t)(s_pack >> 32);
                sel_idx[r] = (int)(~(uint32_t)s_pack);
            }
            __syncthreads();
            last = s_pack;
            __syncthreads();
        }
    }
    __syncthreads();

    const int tg = get_tgt(tgt, row);
    if (tid < BM && sel_idx[tid] == tg) s_has = 1;
    __syncthreads();
    if (!s_has) {
        if (tid == 0) s_pack = ~0ull;
        __syncthreads();
        unsigned long long my = ~0ull;
        if (tid < BM) {
            my = ((unsigned long long)sel_key[tid] << 32) | (uint32_t)(~sel_idx[tid]);
            atomicMin(&s_pack, my);
        }
        __syncthreads();
        if (tid < BM && my == s_pack) {
            sel_idx[tid] = tg;
            sel_key[tid] = f2k(em[(size_t)row*V + tg]);
        }
    }
    __syncthreads();

    if (tid < BM) {
        val[tid] = k2f(sel_key[tid]);
        d_beam_idx[row*BM + tid] = sel_idx[tid];
    }
    __syncthreads();
    if (tid < BM) {
        float er = val[0];
        d_w[(size_t)row*BM + tid] = __expf(val[tid] - er);
        if (tid == 0) d_emref[row] = er;
    }
}

// ============================================================================
// K2: trans (expm1 tiles, fp32x2 FFMA2) + num folded into the same grid.
// ============================================================================
__global__ void __launch_bounds__(256) trans_kernel(
    const float* __restrict__ E1, const float* __restrict__ E2,
    const float* __restrict__ em, const void* __restrict__ tg)
{
    const int tid = threadIdx.x;

    if (blockIdx.x >= NTRANS) {            // ---- num item ----
        __shared__ float nred[8];
        const int b = blockIdx.x - NTRANS;
        float v = 0.f;
        for (int t = tid; t < SS; t += 256) {
            const int row = b*SS + t;
            const int cur = get_tgt(tg, row);
            float x = em[(size_t)row*V + cur];
            if (t > 0) {
                const int pv = get_tgt(tg, row-1);
                const float4* e1 = (const float4*)(E1 + (size_t)pv*RR);
                const float4* e2 = (const float4*)(E2 + (size_t)cur*RR);
                float d = 0.f;
                #pragma unroll
                for (int q = 0; q < 8; q++) {
                    float4 a = e1[q], c = e2[q];
                    d += a.x*c.x + a.y*c.y + a.z*c.z + a.w*c.w;
                }
                x += d;
            }
            v += x;
        }
        #pragma unroll
        for (int o = 16; o; o >>= 1) v += __shfl_xor_sync(0xffffffffu, v, o);
        if ((tid & 31) == 0) nred[tid >> 5] = v;
        __syncthreads();
        if (tid == 0) {
            float s = 0.f;
            for (int i = 0; i < 8; i++) s += nred[i];
            d_num[b] = s;
        }
        return;
    }

    __shared__ float e1t[RR][BM];
    __shared__ float e2t[RR][BM];

    const int bt = blockIdx.x;
    const int b = bt/(SS-1), tm1 = bt%(SS-1);
    const int rowp = b*SS + tm1, rowc = rowp + 1;

    for (int i = tid; i < BM*8; i += 256) {
        int j = i >> 3, q = i & 7;
        float4 v = ((const float4*)(E1 + (size_t)d_beam_idx[rowp*BM + j]*RR))[q];
        e1t[q*4+0][j] = v.x; e1t[q*4+1][j] = v.y;
        e1t[q*4+2][j] = v.z; e1t[q*4+3][j] = v.w;
        float4 u = ((const float4*)(E2 + (size_t)d_beam_idx[rowc*BM + j]*RR))[q];
        e2t[q*4+0][j] = u.x; e2t[q*4+1][j] = u.y;
        e2t[q*4+2][j] = u.z; e2t[q*4+3][j] = u.w;
    }
    __syncthreads();

    const int tj = tid >> 4, tk = tid & 15, j0 = tj*4, k0 = tk*4;
    unsigned long long acc[4][2];
    #pragma unroll
    for (int a = 0; a < 4; a++) { acc[a][0] = 0ull; acc[a][1] = 0ull; }
    #pragma unroll
    for (int r = 0; r < RR; r++) {
        float4 A  = *(const float4*)&e1t[r][j0];
        float4 Bv = *(const float4*)&e2t[r][k0];
        unsigned long long b01 = pk2(Bv.x, Bv.y), b23 = pk2(Bv.z, Bv.w);
        unsigned long long a0 = pk2(A.x, A.x), a1 = pk2(A.y, A.y);
        unsigned long long a2 = pk2(A.z, A.z), a3 = pk2(A.w, A.w);
        acc[0][0] = fma2_(a0, b01, acc[0][0]); acc[0][1] = fma2_(a0, b23, acc[0][1]);
        acc[1][0] = fma2_(a1, b01, acc[1][0]); acc[1][1] = fma2_(a1, b23, acc[1][1]);
        acc[2][0] = fma2_(a2, b01, acc[2][0]); acc[2][1] = fma2_(a2, b23, acc[2][1]);
        acc[3][0] = fma2_(a3, b01, acc[3][0]); acc[3][1] = fma2_(a3, b23, acc[3][1]);
    }

    __half* outp = d_dt + (size_t)bt * BM * BM;
    #pragma unroll
    for (int jj = 0; jj < 4; jj++) {
        float2 p0 = up2(acc[jj][0]), p1 = up2(acc[jj][1]);
        float dv[4] = {p0.x, p0.y, p1.x, p1.y};
        #pragma unroll
        for (int c = 0; c < 4; c++) {       // expm1: t + t^2/2 + t^3/6
            float x = dv[c];
            dv[c] = x * fmaf(x, fmaf(x, 0.166666667f, 0.5f), 1.0f);
        }
        *(__half2*)(outp + (j0+jj)*BM + k0    ) = __floats2half2_rn(dv[0], dv[1]);
        *(__half2*)(outp + (j0+jj)*BM + k0 + 2) = __floats2half2_rn(dv[2], dv[3]);
    }
}

// ============================================================================
// K2b: pair composition. C[j,k] = (sum_m (1+d1[j,m]) w1[m] (1+d2[m,k])) * w2[k]
// One 64x64x64 fp32 GEMM per (b, p); p covers t = 2p+1, 2p+2.
// ============================================================================
__global__ void __launch_bounds__(256) trans2_kernel()
{
    __shared__ float As[BM][BM];     // As[j][m] = (1+d1[j,m]) * w1[m]
    __shared__ float Bs[BM][BM];     // Bs[m][k] = 1+d2[m,k]
    __shared__ float w1s[BM], w2s[BM];

    const int tid = threadIdx.x;
    const int blk = blockIdx.x;
    const int b = blk / NPAIR, p = blk % NPAIR;
    const int tau = 2*p + 1;
    const __half2* d1 = (const __half2*)(d_dt + ((size_t)b*(SS-1) + (tau-1)) * BM * BM);
    const __half2* d2 = (const __half2*)(d_dt + ((size_t)b*(SS-1) + tau    ) * BM * BM);

    if (tid < BM)            w1s[tid]    = d_w[(size_t)(b*SS + tau    )*BM + tid];
    else if (tid < 2*BM)     w2s[tid-BM] = d_w[(size_t)(b*SS + tau + 1)*BM + tid - BM];
    __syncthreads();

    #pragma unroll
    for (int u = 0; u < 8; u++) {
        int lin = tid + u*256;               // 2048 half2 per tile
        int r0 = lin >> 5, c0 = (lin & 31) * 2;
        float2 f1 = __half22float2(d1[lin]);
        As[r0][c0]   = (1.0f + f1.x) * w1s[c0];
        As[r0][c0+1] = (1.0f + f1.y) * w1s[c0+1];
        float2 f2 = __half22float2(d2[lin]);
        Bs[r0][c0]   = 1.0f + f2.x;
        Bs[r0][c0+1] = 1.0f + f2.y;
    }
    __syncthreads();

    const int tj = tid >> 4, tk = tid & 15, j0 = tj*4, k0 = tk*4;
    unsigned long long acc[4][2];
    #pragma unroll
    for (int a = 0; a < 4; a++) { acc[a][0] = 0ull; acc[a][1] = 0ull; }

    #pragma unroll 4
    for (int m = 0; m < BM; m++) {
        float4 Bv = *(const float4*)&Bs[m][k0];
        unsigned long long b01 = pk2(Bv.x, Bv.y), b23 = pk2(Bv.z, Bv.w);
        float A0 = As[j0+0][m], A1 = As[j0+1][m], A2 = As[j0+2][m], A3 = As[j0+3][m];
        unsigned long long a0 = pk2(A0, A0), a1 = pk2(A1, A1);
        unsigned long long a2 = pk2(A2, A2), a3 = pk2(A3, A3);
        acc[0][0] = fma2_(a0, b01, acc[0][0]); acc[0][1] = fma2_(a0, b23, acc[0][1]);
        acc[1][0] = fma2_(a1, b01, acc[1][0]); acc[1][1] = fma2_(a1, b23, acc[1][1]);
        acc[2][0] = fma2_(a2, b01, acc[2][0]); acc[2][1] = fma2_(a2, b23, acc[2][1]);
        acc[3][0] = fma2_(a3, b01, acc[3][0]); acc[3][1] = fma2_(a3, b23, acc[3][1]);
    }

    __half* outp = d_c2 + (size_t)blk * BM * BM;
    const float wk0 = w2s[k0], wk1 = w2s[k0+1], wk2 = w2s[k0+2], wk3 = w2s[k0+3];
    #pragma unroll
    for (int jj = 0; jj < 4; jj++) {
        float2 p0 = up2(acc[jj][0]), p1 = up2(acc[jj][1]);
        *(__half2*)(outp + (j0+jj)*BM + k0    ) = __floats2half2_rn(p0.x*wk0, p0.y*wk1);
        *(__half2*)(outp + (j0+jj)*BM + k0 + 2) = __floats2half2_rn(p1.x*wk2, p1.y*wk3);
    }
}

// ============================================================================
// K3: serial scan — 255 pair steps (dense C matvec) + 1 single step (t=511).
// ============================================================================
__device__ __forceinline__ void sc_prefetch2(int b, int p, __half* dst)
{
    const __half* src = d_c2 + (size_t)(b*NPAIR + p) * BM * BM;
    uint32_t ds = (uint32_t)__cvta_generic_to_shared(dst);
    #pragma unroll
    for (int i = threadIdx.x; i < 512; i += 128)
        asm volatile("cp.async.cg.shared.global [%0],[%1],16;\n"
                     :: "r"(ds + i*16), "l"(src + i*8));
}

__global__ void __launch_bounds__(128) scan_kernel()
{
    __shared__ __align__(16) __half cring[4][4096];   // 32 KB
    __shared__ float spr[BM];
    __shared__ float part[4][BM];
    __shared__ float rhist[NPAIR+2];
    __shared__ float s_r, rbuf[4];

    const int tid = threadIdx.x, b = blockIdx.x;
    const int w = tid >> 5, l = tid & 31;

    if (tid < BM) spr[tid] = d_w[(size_t)(b*SS)*BM + tid];
    if (tid == 0) s_r = 1.0f;

    #pragma unroll
    for (int p = 0; p < 4; p++) {
        sc_prefetch2(b, p, cring[p]);
        asm volatile("cp.async.commit_group;\n");
    }
    __syncthreads();

    for (int p = 0; p < NPAIR; p++) {
        asm volatile("cp.async.wait_group 3;\n");
        __syncthreads();

        const int st = p & 3;
        const float r = s_r;
        const int j0 = w * 16;
        float a0 = 0.f, a1 = 0.f;
        #pragma unroll
        for (int j = 0; j < 16; j++) {
            float q = spr[j0 + j] * r;
            float2 cf = __half22float2(
                *reinterpret_cast<const __half2*>(&cring[st][(j0 + j)*BM + 2*l]));
            a0 = fmaf(q, cf.x, a0);
            a1 = fmaf(q, cf.y, a1);
        }
        part[w][2*l]   = a0;
        part[w][2*l+1] = a1;
        __syncthreads();

        if (tid < BM) {
            float acc = (part[0][tid] + part[1][tid])
                      + (part[2][tid] + part[3][tid]);
            spr[tid] = acc;
            if (tid == 0) s_r = __fdividef(1.0f, acc);
        }
        if (tid == 64) rhist[p] = r;
        if (p + 4 < NPAIR) sc_prefetch2(b, p + 4, cring[(p+4) & 3]);
        asm volatile("cp.async.commit_group;\n");
    }
    __syncthreads();

    // ---- leftover single step t = 511 (d tile 510, w row 511) ----
    {
        const float r = s_r;
        const __half* dt = d_dt + ((size_t)b*(SS-1) + (SS-2)) * BM * BM;
        const int j0 = w * 16;
        float a0 = 0.f, a1 = 0.f, aS = 0.f;
        #pragma unroll
        for (int j = 0; j < 16; j++) {
            float q = spr[j0 + j] * r;
            float2 df = __half22float2(
                *reinterpret_cast<const __half2*>(&dt[(j0 + j)*BM + 2*l]));
            a0 = fmaf(q, df.x, a0);
            a1 = fmaf(q, df.y, a1);
            aS += q;
        }
        part[w][2*l]   = a0 + aS;
        part[w][2*l+1] = a1 + aS;
        if (tid == 64) rhist[NPAIR] = r;
        __syncthreads();
        if (tid < BM) {
            float acc = (part[0][tid] + part[1][tid])
                      + (part[2][tid] + part[3][tid]);
            spr[tid] = acc * d_w[(size_t)(b*SS + SS-1)*BM + tid];
        }
        __syncthreads();
    }

    // den = M + sum(-log r) + log(sum spr)
    float v = (tid < BM) ? spr[tid] : 0.f;
    #pragma unroll
    for (int o = 16; o; o >>= 1) v += __shfl_xor_sync(0xffffffffu, v, o);
    if (l == 0) rbuf[w] = v;
    __syncthreads();
    const float S = (rbuf[0] + rbuf[1]) + (rbuf[2] + rbuf[3]);
    __syncthreads();

    float lc = 0.f;
    for (int p = tid; p <= NPAIR; p += 128) lc -= logf(rhist[p]);
    #pragma unroll
    for (int o = 16; o; o >>= 1) lc += __shfl_xor_sync(0xffffffffu, lc, o);
    if (l == 0) rbuf[w] = lc;
    __syncthreads();
    const float LC = (rbuf[0] + rbuf[1]) + (rbuf[2] + rbuf[3]);
    __syncthreads();

    float mv = 0.f;
    for (int t = tid; t < SS; t += 128) mv += d_emref[b*SS + t];
    #pragma unroll
    for (int o = 16; o; o >>= 1) mv += __shfl_xor_sync(0xffffffffu, mv, o);
    if (l == 0) rbuf[w] = mv;
    __syncthreads();
    const float M = (rbuf[0] + rbuf[1]) + (rbuf[2] + rbuf[3]);

    if (tid == 0) d_den[b] = M + LC + logf(S);
}

// ============================================================================
// epilogue
// ============================================================================
__global__ void out_kernel(float* __restrict__ out, int out_size)
{
    __shared__ float ll[BB];
    const int t = threadIdx.x;
    if (t < BB) ll[t] = d_num[t] - d_den[t];
    __syncthreads();
    if (t == 0) {
        float sum = 0.f;
        for (int i = 0; i < BB; i++) sum += ll[i];
        if (out_size > BB) {
            out[0] = sum;
            for (int i = 0; i < BB; i++) out[1+i] = ll[i];
        } else if (out_size == BB) {
            for (int i = 0; i < BB; i++) out[i] = ll[i];
        } else {
            out[0] = sum;
        }
    }
}

// ============================================================================
extern "C" void kernel_launch(void* const* d_in, const int* in_sizes, int n_in,
                              void* d_out, int out_size)
{
    const float* em = (const float*)d_in[0];
    const void*  tg = d_in[1];
    const float* E1 = (const float*)d_in[3];
    const float* E2 = (const float*)d_in[4];
    float* out = (float*)d_out;

    detect_kernel<<<1, 256>>>((const int*)tg);
    topk_kernel<<<ROWS, 256>>>(em, tg);
    trans_kernel<<<NTRANS + BB, 256>>>(E1, E2, em, tg);
    trans2_kernel<<<BB*NPAIR, 256>>>();
    scan_kernel<<<BB, 128>>>();
    out_kernel<<<1, 32>>>(out, out_size);
}

// round 7
// speedup vs baseline: 2.7924x; 1.3959x over previous
#include <cuda_runtime.h>
#include <cuda_fp16.h>
#include <cstdint>

#define V     32000
#define BB    8
#define SS    512
#define RR    32
#define BM    64
#define ROWS  (BB*SS)
#define CAP   1024
#define NTRANS (BB*(SS-1))
#define SMS   72   /* padded smem row stride in halves (conflict-free LDSM) */

// ---------------- device scratch (allocation-free rule) ----------------
__device__ int    d_beam_idx[ROWS*BM];
__device__ float  d_w[ROWS*BM];                      // exp(em - em_ref), <= 1
__device__ float  d_emref[ROWS];
__device__ __half d_bufA[(size_t)BB*512*BM*BM];      // 33.5 MB tree ping
__device__ __half d_bufB[(size_t)BB*256*BM*BM];      // 16.7 MB tree pong
__device__ float  d_sA[BB*512], d_sB[BB*256];        // log-scales
__device__ float  d_num[BB], d_den[BB];
__device__ int    d_i64flag;

// ---------------- helpers ----------------
__device__ __forceinline__ int get_tgt(const void* __restrict__ tg, int row){
    if (d_i64flag) return (int)((const long long*)tg)[row];
    return ((const int*)tg)[row];
}
__device__ __forceinline__ uint32_t f2k(float f){
    uint32_t u = __float_as_uint(f);
    return (u & 0x80000000u) ? ~u : (u | 0x80000000u);
}
__device__ __forceinline__ float k2f(uint32_t k){
    uint32_t u = (k & 0x80000000u) ? (k ^ 0x80000000u) : ~k;
    return __uint_as_float(u);
}
__device__ __forceinline__ unsigned long long pk2(float a, float b){
    unsigned long long r; asm("mov.b64 %0,{%1,%2};" : "=l"(r) : "f"(a), "f"(b)); return r;
}
__device__ __forceinline__ unsigned long long fma2_(unsigned long long a,
        unsigned long long b, unsigned long long c){
    unsigned long long d;
    asm("fma.rn.f32x2 %0,%1,%2,%3;" : "=l"(d) : "l"(a), "l"(b), "l"(c));
    return d;
}
__device__ __forceinline__ float2 up2(unsigned long long p){
    float2 f; asm("mov.b64 {%0,%1},%2;" : "=f"(f.x), "=f"(f.y) : "l"(p)); return f;
}

__global__ void detect_kernel(const int* __restrict__ tg32){
    __shared__ int s_or;
    if (threadIdx.x == 0) s_or = 0;
    __syncthreads();
    int acc = 0;
    for (int i = threadIdx.x; i < ROWS/2; i += 256) acc |= tg32[2*i + 1];
    atomicOr(&s_or, acc);
    __syncthreads();
    if (threadIdx.x == 0) d_i64flag = (s_or == 0) ? 1 : 0;
}

// ============================================================================
// K1: exact top-64 per row (R3/R6-proven)
// ============================================================================
__global__ void __launch_bounds__(256) topk_kernel(
    const float* __restrict__ em, const void* __restrict__ tgt)
{
    __shared__ unsigned long long cand[CAP];
    __shared__ int s_cnt, s_has;
    __shared__ unsigned long long s_pack;
    __shared__ int      sel_idx[BM];
    __shared__ uint32_t sel_key[BM];
    __shared__ float    val[BM];

    const int tid = threadIdx.x, row = blockIdx.x;
    const float4* rp = (const float4*)(em + (size_t)row * V);
    const uint32_t THR = f2k(2.5f);

    if (tid == 0) { s_cnt = 0; s_has = 0; }
    __syncthreads();

    #pragma unroll 4
    for (int i = tid; i < V/4; i += 256) {
        float4 v = rp[i];
        float f[4] = {v.x, v.y, v.z, v.w};
        #pragma unroll
        for (int c = 0; c < 4; c++) {
            uint32_t k = f2k(f[c]);
            if (k > THR) {
                int p = atomicAdd(&s_cnt, 1);
                if (p < CAP)
                    cand[p] = ((unsigned long long)k << 32) | (uint32_t)(~(4*i + c));
            }
        }
    }
    __syncthreads();
    const int cnt = s_cnt;

    if (cnt >= BM && cnt <= CAP) {
        for (int ci = tid; ci < cnt; ci += 256) {
            unsigned long long e = cand[ci];
            int rank = 0;
            for (int cj = 0; cj < cnt; cj++) rank += (cand[cj] > e);
            if (rank < BM) {
                sel_key[rank] = (uint32_t)(e >> 32);
                sel_idx[rank] = (int)(~(uint32_t)e);
            }
        }
    } else {
        unsigned long long last = ~0ull;
        for (int r = 0; r < BM; r++) {
            if (tid == 0) s_pack = 0ull;
            __syncthreads();
            unsigned long long lm = 0ull;
            for (int i = tid; i < V; i += 256) {
                uint32_t k = f2k(em[(size_t)row*V + i]);
                unsigned long long pk = ((unsigned long long)k << 32) | (uint32_t)(~i);
                if (pk < last && pk > lm) lm = pk;
            }
            atomicMax(&s_pack, lm);
            __syncthreads();
            if (tid == 0) {
                sel_key[r] = (uint32_t)(s_pack >> 32);
                sel_idx[r] = (int)(~(uint32_t)s_pack);
            }
            __syncthreads();
            last = s_pack;
            __syncthreads();
        }
    }
    __syncthreads();

    const int tg = get_tgt(tgt, row);
    if (tid < BM && sel_idx[tid] == tg) s_has = 1;
    __syncthreads();
    if (!s_has) {
        if (tid == 0) s_pack = ~0ull;
        __syncthreads();
        unsigned long long my = ~0ull;
        if (tid < BM) {
            my = ((unsigned long long)sel_key[tid] << 32) | (uint32_t)(~sel_idx[tid]);
            atomicMin(&s_pack, my);
        }
        __syncthreads();
        if (tid < BM && my == s_pack) {
            sel_idx[tid] = tg;
            sel_key[tid] = f2k(em[(size_t)row*V + tg]);
        }
    }
    __syncthreads();

    if (tid < BM) {
        val[tid] = k2f(sel_key[tid]);
        d_beam_idx[row*BM + tid] = sel_idx[tid];
    }
    __syncthreads();
    if (tid < BM) {
        float er = val[0];
        d_w[(size_t)row*BM + tid] = __expf(val[tid] - er);
        if (tid == 0) d_emref[row] = er;
    }
}

// ============================================================================
// K2: leaf emission (A_t = exp(tr)*w[k], fp16) + diag(w0) leaves + num items.
// ============================================================================
__global__ void __launch_bounds__(256) trans_kernel(
    const float* __restrict__ E1, const float* __restrict__ E2,
    const float* __restrict__ em, const void* __restrict__ tg)
{
    const int tid = threadIdx.x;

    if (blockIdx.x >= NTRANS + BB) {       // ---- num item ----
        __shared__ float nred[8];
        const int b = blockIdx.x - NTRANS - BB;
        float v = 0.f;
        for (int t = tid; t < SS; t += 256) {
            const int row = b*SS + t;
            const int cur = get_tgt(tg, row);
            float x = em[(size_t)row*V + cur];
            if (t > 0) {
                const int pv = get_tgt(tg, row-1);
                const float4* e1 = (const float4*)(E1 + (size_t)pv*RR);
                const float4* e2 = (const float4*)(E2 + (size_t)cur*RR);
                float d = 0.f;
                #pragma unroll
                for (int q = 0; q < 8; q++) {
                    float4 a = e1[q], c = e2[q];
                    d += a.x*c.x + a.y*c.y + a.z*c.z + a.w*c.w;
                }
                x += d;
            }
            v += x;
        }
        #pragma unroll
        for (int o = 16; o; o >>= 1) v += __shfl_xor_sync(0xffffffffu, v, o);
        if ((tid & 31) == 0) nred[tid >> 5] = v;
        __syncthreads();
        if (tid == 0) {
            float s = 0.f;
            for (int i = 0; i < 8; i++) s += nred[i];
            d_num[b] = s;
        }
        return;
    }

    if (blockIdx.x >= NTRANS) {            // ---- diag(w0) leaf ----
        const int b = blockIdx.x - NTRANS;
        __half* outp = d_bufA + ((size_t)b*512) * 4096;
        const float* w0 = d_w + (size_t)(b*SS)*BM;
        for (int i = tid; i < 4096; i += 256) {
            int j = i >> 6, k = i & 63;
            outp[i] = __float2half((j == k) ? w0[j] : 0.f);
        }
        if (tid == 0) d_sA[b*512] = 0.f;
        return;
    }

    __shared__ float e1t[RR][BM];
    __shared__ float e2t[RR][BM];

    const int bt = blockIdx.x;
    const int b = bt/(SS-1), tm1 = bt%(SS-1);
    const int rowp = b*SS + tm1, rowc = rowp + 1;
    const int t = tm1 + 1;

    for (int i = tid; i < BM*8; i += 256) {
        int j = i >> 3, q = i & 7;
        float4 v = ((const float4*)(E1 + (size_t)d_beam_idx[rowp*BM + j]*RR))[q];
        e1t[q*4+0][j] = v.x; e1t[q*4+1][j] = v.y;
        e1t[q*4+2][j] = v.z; e1t[q*4+3][j] = v.w;
        float4 u = ((const float4*)(E2 + (size_t)d_beam_idx[rowc*BM + j]*RR))[q];
        e2t[q*4+0][j] = u.x; e2t[q*4+1][j] = u.y;
        e2t[q*4+2][j] = u.z; e2t[q*4+3][j] = u.w;
    }
    __syncthreads();

    const int tj = tid >> 4, tk = tid & 15, j0 = tj*4, k0 = tk*4;
    unsigned long long acc[4][2];
    #pragma unroll
    for (int a = 0; a < 4; a++) { acc[a][0] = 0ull; acc[a][1] = 0ull; }
    #pragma unroll
    for (int r = 0; r < RR; r++) {
        float4 A  = *(const float4*)&e1t[r][j0];
        float4 Bv = *(const float4*)&e2t[r][k0];
        unsigned long long b01 = pk2(Bv.x, Bv.y), b23 = pk2(Bv.z, Bv.w);
        unsigned long long a0 = pk2(A.x, A.x), a1 = pk2(A.y, A.y);
        unsigned long long a2 = pk2(A.z, A.z), a3 = pk2(A.w, A.w);
        acc[0][0] = fma2_(a0, b01, acc[0][0]); acc[0][1] = fma2_(a0, b23, acc[0][1]);
        acc[1][0] = fma2_(a1, b01, acc[1][0]); acc[1][1] = fma2_(a1, b23, acc[1][1]);
        acc[2][0] = fma2_(a2, b01, acc[2][0]); acc[2][1] = fma2_(a2, b23, acc[2][1]);
        acc[3][0] = fma2_(a3, b01, acc[3][0]); acc[3][1] = fma2_(a3, b23, acc[3][1]);
    }

    // leaf[j][k] = (1 + expm1(tr)) * w_t[k]
    __half* outp = d_bufA + ((size_t)b*512 + t) * 4096;
    const float4 wv = *(const float4*)(d_w + (size_t)rowc*BM + k0);
    const float wk[4] = {wv.x, wv.y, wv.z, wv.w};
    #pragma unroll
    for (int jj = 0; jj < 4; jj++) {
        float2 p0 = up2(acc[jj][0]), p1 = up2(acc[jj][1]);
        float dv[4] = {p0.x, p0.y, p1.x, p1.y};
        #pragma unroll
        for (int c = 0; c < 4; c++) {       // exp(x) ~ 1 + x + x^2/2 + x^3/6
            float x = dv[c];
            dv[c] = wk[c] * fmaf(x, fmaf(x, fmaf(x, 0.166666667f, 0.5f), 1.0f), 1.0f);
        }
        *(__half2*)(outp + (j0+jj)*BM + k0    ) = __floats2half2_rn(dv[0], dv[1]);
        *(__half2*)(outp + (j0+jj)*BM + k0 + 2) = __floats2half2_rn(dv[2], dv[3]);
    }
    if (tid == 0) d_sA[b*512 + t] = 0.f;
}

// ============================================================================
// K3: one tree level. dst[i] = normalize(src[2i] x src[2i+1]); HMMA fp16 GEMM.
// 128 threads = 4 warps, warp w owns output rows [16w, 16w+16).
// ============================================================================
__global__ void __launch_bounds__(128) gemm_level(
    const __half* __restrict__ src, __half* __restrict__ dst,
    const float* __restrict__ ss, float* __restrict__ ds,
    int ndst, int sstride, int dstride)
{
    __shared__ __align__(16) __half As[64*SMS];
    __shared__ __align__(16) __half Bs[64*SMS];
    __shared__ float red[4];

    const int tid = threadIdx.x, lane = tid & 31, w = tid >> 5;
    const int b = blockIdx.x / ndst, i = blockIdx.x % ndst;
    const size_t s0 = ((size_t)b*sstride + 2*i) * 4096;

    const uint32_t aA = (uint32_t)__cvta_generic_to_shared(As);
    const uint32_t aB = (uint32_t)__cvta_generic_to_shared(Bs);
    #pragma unroll
    for (int c = 0; c < 4; c++) {
        int chunk = tid + c*128;           // 512 x 16B chunks per matrix
        int j = chunk >> 3, q = chunk & 7;
        asm volatile("cp.async.cg.shared.global [%0],[%1],16;\n"
            :: "r"(aA + (uint32_t)(j*SMS + q*8)*2), "l"(src + s0 + j*64 + q*8));
        asm volatile("cp.async.cg.shared.global [%0],[%1],16;\n"
            :: "r"(aB + (uint32_t)(j*SMS + q*8)*2), "l"(src + s0 + 4096 + j*64 + q*8));
    }
    asm volatile("cp.async.commit_group;\n");
    asm volatile("cp.async.wait_group 0;\n");
    __syncthreads();

    float acc[8][4];
    #pragma unroll
    for (int nt = 0; nt < 8; nt++)
        #pragma unroll
        for (int q = 0; q < 4; q++) acc[nt][q] = 0.f;

    const int r16 = lane & 15, chi = lane >> 4;
    #pragma unroll
    for (int ks = 0; ks < 4; ks++) {
        uint32_t a0, a1, a2, a3;
        uint32_t addrA = aA + (uint32_t)((16*w + r16)*SMS + ks*16 + chi*8)*2;
        asm volatile("ldmatrix.sync.aligned.m8n8.x4.shared.b16 {%0,%1,%2,%3},[%4];"
            : "=r"(a0), "=r"(a1), "=r"(a2), "=r"(a3) : "r"(addrA));
        #pragma unroll
        for (int nt = 0; nt < 8; nt++) {
            uint32_t b0, b1;
            uint32_t addrB = aB + (uint32_t)((ks*16 + r16)*SMS + nt*8)*2;
            asm volatile("ldmatrix.sync.aligned.m8n8.x2.trans.shared.b16 {%0,%1},[%2];"
                : "=r"(b0), "=r"(b1) : "r"(addrB));
            asm volatile("mma.sync.aligned.m16n8k16.row.col.f32.f16.f16.f32 "
                "{%0,%1,%2,%3},{%4,%5,%6,%7},{%8,%9},{%0,%1,%2,%3};"
                : "+f"(acc[nt][0]), "+f"(acc[nt][1]), "+f"(acc[nt][2]), "+f"(acc[nt][3])
                : "r"(a0), "r"(a1), "r"(a2), "r"(a3), "r"(b0), "r"(b1));
        }
    }

    // block max (all entries >= 0)
    float mx = 0.f;
    #pragma unroll
    for (int nt = 0; nt < 8; nt++)
        #pragma unroll
        for (int q = 0; q < 4; q++) mx = fmaxf(mx, acc[nt][q]);
    #pragma unroll
    for (int o = 16; o; o >>= 1) mx = fmaxf(mx, __shfl_xor_sync(0xffffffffu, mx, o));
    if (lane == 0) red[w] = mx;
    __syncthreads();
    mx = fmaxf(fmaxf(red[0], red[1]), fmaxf(red[2], red[3]));
    const float inv = __fdividef(1.0f, mx);

    __half* op = dst + ((size_t)b*dstride + i) * 4096;
    const int m0 = 16*w + (lane >> 2), nc = (lane & 3)*2;
    #pragma unroll
    for (int nt = 0; nt < 8; nt++) {
        *(__half2*)(op + m0*64 + nt*8 + nc) =
            __floats2half2_rn(acc[nt][0]*inv, acc[nt][1]*inv);
        *(__half2*)(op + (m0+8)*64 + nt*8 + nc) =
            __floats2half2_rn(acc[nt][2]*inv, acc[nt][3]*inv);
    }
    if (tid == 0)
        ds[b*dstride + i] = ss[b*sstride + 2*i] + ss[b*sstride + 2*i + 1] + logf(mx);
}

// ============================================================================
// K4: den[b] = M + s_root + log(sum of root entries)
// ============================================================================
__global__ void __launch_bounds__(256) den_kernel()
{
    __shared__ float rbuf[8];
    const int tid = threadIdx.x, b = blockIdx.x;
    const int w = tid >> 5, l = tid & 31;

    const __half2* root = (const __half2*)(d_bufB + (size_t)b*256*4096);
    float s = 0.f;
    for (int i = tid; i < 2048; i += 256) {
        float2 f = __half22float2(root[i]);
        s += f.x + f.y;
    }
    #pragma unroll
    for (int o = 16; o; o >>= 1) s += __shfl_xor_sync(0xffffffffu, s, o);
    if (l == 0) rbuf[w] = s;
    __syncthreads();
    float S = 0.f;
    if (tid == 0) for (int i = 0; i < 8; i++) S += rbuf[i];
    __syncthreads();

    float mv = 0.f;
    for (int t = tid; t < SS; t += 256) mv += d_emref[b*SS + t];
    #pragma unroll
    for (int o = 16; o; o >>= 1) mv += __shfl_xor_sync(0xffffffffu, mv, o);
    if (l == 0) rbuf[w] = mv;
    __syncthreads();
    if (tid == 0) {
        float M = 0.f;
        for (int i = 0; i < 8; i++) M += rbuf[i];
        d_den[b] = M + d_sB[b*256] + logf(S);
    }
}

// ============================================================================
// epilogue
// ============================================================================
__global__ void out_kernel(float* __restrict__ out, int out_size)
{
    __shared__ float ll[BB];
    const int t = threadIdx.x;
    if (t < BB) ll[t] = d_num[t] - d_den[t];
    __syncthreads();
    if (t == 0) {
        float sum = 0.f;
        for (int i = 0; i < BB; i++) sum += ll[i];
        if (out_size > BB) {
            out[0] = sum;
            for (int i = 0; i < BB; i++) out[1+i] = ll[i];
        } else if (out_size == BB) {
            for (int i = 0; i < BB; i++) out[i] = ll[i];
        } else {
            out[0] = sum;
        }
    }
}

// ============================================================================
extern "C" void kernel_launch(void* const* d_in, const int* in_sizes, int n_in,
                              void* d_out, int out_size)
{
    const float* em = (const float*)d_in[0];
    const void*  tg = d_in[1];
    const float* E1 = (const float*)d_in[3];
    const float* E2 = (const float*)d_in[4];
    float* out = (float*)d_out;

    detect_kernel<<<1, 256>>>((const int*)tg);
    topk_kernel<<<ROWS, 256>>>(em, tg);
    trans_kernel<<<NTRANS + 2*BB, 256>>>(E1, E2, em, tg);

    __half *bufA = nullptr, *bufB = nullptr;
    float  *sA = nullptr, *sB = nullptr;
    cudaGetSymbolAddress((void**)&bufA, d_bufA);
    cudaGetSymbolAddress((void**)&bufB, d_bufB);
    cudaGetSymbolAddress((void**)&sA, d_sA);
    cudaGetSymbolAddress((void**)&sB, d_sB);

    // tree: 512 -> 256 -> 128 -> 64 -> 32 -> 16 -> 8 -> 4 -> 2 -> 1
    gemm_level<<<BB*256, 128>>>(bufA, bufB, sA, sB, 256, 512, 256);
    gemm_level<<<BB*128, 128>>>(bufB, bufA, sB, sA, 128, 256, 512);
    gemm_level<<<BB* 64, 128>>>(bufA, bufB, sA, sB,  64, 512, 256);
    gemm_level<<<BB* 32, 128>>>(bufB, bufA, sB, sA,  32, 256, 512);
    gemm_level<<<BB* 16, 128>>>(bufA, bufB, sA, sB,  16, 512, 256);
    gemm_level<<<BB*  8, 128>>>(bufB, bufA, sB, sA,   8, 256, 512);
    gemm_level<<<BB*  4, 128>>>(bufA, bufB, sA, sB,   4, 512, 256);
    gemm_level<<<BB*  2, 128>>>(bufB, bufA, sB, sA,   2, 256, 512);
    gemm_level<<<BB*  1, 128>>>(bufA, bufB, sA, sB,   1, 512, 256);

    den_kernel<<<BB, 256>>>();
    out_kernel<<<1, 32>>>(out, out_size);
}

// round 8
// speedup vs baseline: 3.4466x; 1.2343x over previous
#include <cuda_runtime.h>
#include <cuda_fp16.h>
#include <cstdint>

#define V     32000
#define BB    8
#define SS    512
#define RR    32
#define BM    64
#define ROWS  (BB*SS)
#define CAP   1024
#define SMS   72   /* padded smem row stride (halves) for 64-wide tiles */
#define ASTR  40   /* padded stride for 32-wide E1 tiles */

// ---------------- device scratch (allocation-free rule) ----------------
__device__ int    d_beam_idx[ROWS*BM];
__device__ float  d_w[ROWS*BM];                      // exp(em - em_ref)
__device__ float  d_emref[ROWS];
__device__ __half d_bufA[(size_t)BB*256*BM*BM];      // 16.7 MB tree ping
__device__ __half d_bufB[(size_t)BB*128*BM*BM];      // 8.4 MB tree pong
__device__ float  d_sA[BB*256], d_sB[BB*128];        // log-scales
__device__ float  d_numpart[64];
__device__ float  d_den[BB];
__device__ int    d_i64flag;

// ---------------- helpers ----------------
__device__ __forceinline__ int get_tgt(const void* __restrict__ tg, int row){
    if (d_i64flag) return (int)((const long long*)tg)[row];
    return ((const int*)tg)[row];
}
__device__ __forceinline__ uint32_t f2k(float f){
    uint32_t u = __float_as_uint(f);
    return (u & 0x80000000u) ? ~u : (u | 0x80000000u);
}
__device__ __forceinline__ float k2f(uint32_t k){
    uint32_t u = (k & 0x80000000u) ? (k ^ 0x80000000u) : ~k;
    return __uint_as_float(u);
}
// exp(x) for |x| < 0.02: 1 + x(1 + x(1/2 + x/6))
__device__ __forceinline__ float pexp(float x){
    return fmaf(x, fmaf(x, fmaf(x, 0.166666667f, 0.5f), 1.0f), 1.0f);
}

__global__ void detect_kernel(const int* __restrict__ tg32){
    __shared__ int s_or;
    if (threadIdx.x == 0) s_or = 0;
    __syncthreads();
    int acc = 0;
    for (int i = threadIdx.x; i < ROWS/2; i += 256) acc |= tg32[2*i + 1];
    atomicOr(&s_or, acc);
    __syncthreads();
    if (threadIdx.x == 0) d_i64flag = (s_or == 0) ? 1 : 0;
}

// ============================================================================
// shared MMA core: C(64x64) += A(64 x 16*ksteps) * B(16*ksteps x 64)
// A row-major smem (stride astrH halves), B row-major smem (stride SMS).
// 4 warps; warp w owns rows [16w,16w+16). Proven layout from R7 gemm_level.
// ============================================================================
__device__ __forceinline__ void mma64(uint32_t aA, uint32_t aB,
                                      float acc[8][4], int ksteps, int astrH)
{
    const int lane = threadIdx.x & 31, w = (threadIdx.x >> 5) & 3;
    const int r16 = lane & 15, chi = lane >> 4;
    for (int ks = 0; ks < ksteps; ks++) {
        uint32_t a0, a1, a2, a3;
        uint32_t addrA = aA + (uint32_t)((16*w + r16)*astrH + ks*16 + chi*8)*2;
        asm volatile("ldmatrix.sync.aligned.m8n8.x4.shared.b16 {%0,%1,%2,%3},[%4];"
            : "=r"(a0), "=r"(a1), "=r"(a2), "=r"(a3) : "r"(addrA));
        #pragma unroll
        for (int nt = 0; nt < 8; nt++) {
            uint32_t b0, b1;
            uint32_t addrB = aB + (uint32_t)((ks*16 + r16)*SMS + nt*8)*2;
            asm volatile("ldmatrix.sync.aligned.m8n8.x2.trans.shared.b16 {%0,%1},[%2];"
                : "=r"(b0), "=r"(b1) : "r"(addrB));
            asm volatile("mma.sync.aligned.m16n8k16.row.col.f32.f16.f16.f32 "
                "{%0,%1,%2,%3},{%4,%5,%6,%7},{%8,%9},{%0,%1,%2,%3};"
                : "+f"(acc[nt][0]), "+f"(acc[nt][1]), "+f"(acc[nt][2]), "+f"(acc[nt][3])
                : "r"(a0), "r"(a1), "r"(a2), "r"(a3), "r"(b0), "r"(b1));
        }
    }
}
__device__ __forceinline__ void acc_zero(float acc[8][4]){
    #pragma unroll
    for (int nt = 0; nt < 8; nt++)
        #pragma unroll
        for (int q = 0; q < 4; q++) acc[nt][q] = 0.f;
}
// block max over acc (entries >= 0). Includes the necessary barrier.
__device__ __forceinline__ float blockmax(const float acc[8][4], float* red)
{
    const int lane = threadIdx.x & 31, w = (threadIdx.x >> 5) & 3;
    float mx = 0.f;
    #pragma unroll
    for (int nt = 0; nt < 8; nt++)
        #pragma unroll
        for (int q = 0; q < 4; q++) mx = fmaxf(mx, acc[nt][q]);
    #pragma unroll
    for (int o = 16; o; o >>= 1) mx = fmaxf(mx, __shfl_xor_sync(0xffffffffu, mx, o));
    if (lane == 0) red[w] = mx;
    __syncthreads();
    return fmaxf(fmaxf(red[0], red[1]), fmaxf(red[2], red[3]));
}
// store normalized acc fragments: row-major, stride strH halves (smem or gmem)
__device__ __forceinline__ void store_frag(__half* op, const float acc[8][4],
                                           float inv, int strH)
{
    const int lane = threadIdx.x & 31, w = (threadIdx.x >> 5) & 3;
    const int m0 = 16*w + (lane >> 2), nc = (lane & 3)*2;
    #pragma unroll
    for (int nt = 0; nt < 8; nt++) {
        *(__half2*)(op + m0*strH + nt*8 + nc) =
            __floats2half2_rn(acc[nt][0]*inv, acc[nt][1]*inv);
        *(__half2*)(op + (m0+8)*strH + nt*8 + nc) =
            __floats2half2_rn(acc[nt][2]*inv, acc[nt][3]*inv);
    }
}

// ============================================================================
// K1: exact top-64 per row. Hot loop uses signed-int threshold compare.
// ============================================================================
__global__ void __launch_bounds__(256) topk_kernel(
    const float* __restrict__ em, const void* __restrict__ tgt)
{
    __shared__ unsigned long long cand[CAP];   // (float bits <<32) | ~idx
    __shared__ int s_cnt, s_has;
    __shared__ unsigned long long s_pack;
    __shared__ int      sel_idx[BM];
    __shared__ uint32_t sel_key[BM];           // RAW float bits
    __shared__ float    val[BM];

    const int tid = threadIdx.x, row = blockIdx.x;
    const float4* rp = (const float4*)(em + (size_t)row * V);
    const int THRI = 0x40200000;               // bits(2.5f); f>2.5 <=> (int)bits>THRI

    if (tid == 0) { s_cnt = 0; s_has = 0; }
    __syncthreads();

    #pragma unroll 4
    for (int i = tid; i < V/4; i += 256) {
        float4 v = rp[i];
        int bi[4] = {__float_as_int(v.x), __float_as_int(v.y),
                     __float_as_int(v.z), __float_as_int(v.w)};
        #pragma unroll
        for (int c = 0; c < 4; c++) {
            if (bi[c] > THRI) {
                int p = atomicAdd(&s_cnt, 1);
                if (p < CAP)
                    cand[p] = ((unsigned long long)(uint32_t)bi[c] << 32)
                            | (uint32_t)(~(4*i + c));
            }
        }
    }
    __syncthreads();
    const int cnt = s_cnt;

    if (cnt >= BM && cnt <= CAP) {
        for (int ci = tid; ci < cnt; ci += 256) {
            unsigned long long e = cand[ci];
            int rank = 0;
            for (int cj = 0; cj < cnt; cj++) rank += (cand[cj] > e);
            if (rank < BM) {
                sel_key[rank] = (uint32_t)(e >> 32);
                sel_idx[rank] = (int)(~(uint32_t)e);
            }
        }
    } else {
        // exact fallback (never on bench data): 64 rounds of max extraction
        unsigned long long last = ~0ull;
        for (int r = 0; r < BM; r++) {
            if (tid == 0) s_pack = 0ull;
            __syncthreads();
            unsigned long long lm = 0ull;
            for (int i = tid; i < V; i += 256) {
                uint32_t k = f2k(em[(size_t)row*V + i]);
                unsigned long long pk = ((unsigned long long)k << 32) | (uint32_t)(~i);
                if (pk < last && pk > lm) lm = pk;
            }
            atomicMax(&s_pack, lm);
            __syncthreads();
            if (tid == 0) {
                sel_key[r] = __float_as_uint(k2f((uint32_t)(s_pack >> 32)));
                sel_idx[r] = (int)(~(uint32_t)s_pack);
            }
            __syncthreads();
            last = s_pack;
            __syncthreads();
        }
    }
    __syncthreads();

    // force target into beam (drop min-value / max-index element)
    const int tg = get_tgt(tgt, row);
    if (tid < BM && sel_idx[tid] == tg) s_has = 1;
    __syncthreads();
    if (!s_has) {
        if (tid == 0) s_pack = ~0ull;
        __syncthreads();
        unsigned long long my = ~0ull;
        if (tid < BM) {
            my = ((unsigned long long)f2k(__uint_as_float(sel_key[tid])) << 32)
               | (uint32_t)(~sel_idx[tid]);
            atomicMin(&s_pack, my);
        }
        __syncthreads();
        if (tid < BM && my == s_pack) {
            sel_idx[tid] = tg;
            sel_key[tid] = __float_as_uint(em[(size_t)row*V + tg]);
        }
    }
    __syncthreads();

    if (tid < BM) {
        val[tid] = __uint_as_float(sel_key[tid]);
        d_beam_idx[row*BM + tid] = sel_idx[tid];
    }
    __syncthreads();
    if (tid < BM) {
        float er = val[0];
        d_w[(size_t)row*BM + tid] = __expf(val[tid] - er);
        if (tid == 0) d_emref[row] = er;
    }
}

// ============================================================================
// K2: FUSED leaf + tree level 0.  Block (b,i) computes
//   node_i = normalize( A_{2i} * A_{2i+1} ),  A_t = exp(E1[beam_{t-1}]E2[beam_t]^T)*diag(w_t)
//   i = 0: node_0 = normalize( diag(w_0) * A_1 )
// ============================================================================
__global__ void __launch_bounds__(128) leaf_l0_kernel(
    const float* __restrict__ E1, const float* __restrict__ E2)
{
    __shared__ __align__(16) __half E1s[64*ASTR];   // 5 KB
    __shared__ __align__(16) __half E2T[32*SMS];    // 4.6 KB (transposed: [r][n])
    __shared__ __align__(16) __half Ls1[64*SMS];    // 9.2 KB
    __shared__ __align__(16) __half Ls2[64*SMS];    // 9.2 KB
    __shared__ float ws1[BM], ws2[BM], red[4];

    const int tid = threadIdx.x;
    const int b = blockIdx.x >> 8, i = blockIdx.x & 255;
    const int lane = tid & 31, w = tid >> 5;

    // beam rows involved
    const int ra = (i == 0) ? (b*SS)     : (b*SS + 2*i - 1);  // E1 rows, GEMM1
    const int rb = (i == 0) ? (b*SS + 1) : (b*SS + 2*i);      // E2 rows, GEMM1
    const int rc = b*SS + 2*i + 1;                            // E2 rows, GEMM2 (i>0)

    // ws1: i==0 -> w_0 (row scale). i>0 -> w_{2i} (col scale of leaf1)
    if (tid < 64)       ws1[tid]    = d_w[(size_t)((i==0) ? b*SS : rb)*BM + tid];
    else                ws2[tid-64] = d_w[(size_t)((i==0) ? rb   : rc)*BM + tid-64];

    const uint32_t aE1 = (uint32_t)__cvta_generic_to_shared(E1s);
    const uint32_t aE2 = (uint32_t)__cvta_generic_to_shared(E2T);
    const uint32_t aL1 = (uint32_t)__cvta_generic_to_shared(Ls1);
    const uint32_t aL2 = (uint32_t)__cvta_generic_to_shared(Ls2);

    // ---- gather phase 1: E1[beam[ra]] -> E1s, E2[beam[rb]]^T -> E2T ----
    for (int task = tid; task < 512; task += 128) {
        int j = task >> 3, q = task & 7;
        float4 v = ((const float4*)(E1 + (size_t)d_beam_idx[ra*BM + j]*RR))[q];
        __half2 h0 = __floats2half2_rn(v.x, v.y), h1 = __floats2half2_rn(v.z, v.w);
        *(uint2*)&E1s[j*ASTR + q*4] =
            make_uint2(*(uint32_t*)&h0, *(uint32_t*)&h1);
        float4 u = ((const float4*)(E2 + (size_t)d_beam_idx[rb*BM + j]*RR))[q];
        E2T[(4*q+0)*SMS + j] = __float2half_rn(u.x);
        E2T[(4*q+1)*SMS + j] = __float2half_rn(u.y);
        E2T[(4*q+2)*SMS + j] = __float2half_rn(u.z);
        E2T[(4*q+3)*SMS + j] = __float2half_rn(u.w);
    }
    __syncthreads();

    float acc[8][4];
    acc_zero(acc);
    mma64(aE1, aE2, acc, 2, ASTR);          // tr (64x64, K=32)

    const int m0 = 16*w + (lane >> 2), nc = (lane & 3)*2;

    if (i == 0) {
        // P[j][k] = w0[j] * exp(tr)[j][k] * w1[k]
        #pragma unroll
        for (int nt = 0; nt < 8; nt++) {
            float k0 = ws2[nt*8+nc], k1 = ws2[nt*8+nc+1];
            float r0 = ws1[m0], r1 = ws1[m0+8];
            acc[nt][0] = pexp(acc[nt][0])*k0*r0;
            acc[nt][1] = pexp(acc[nt][1])*k1*r0;
            acc[nt][2] = pexp(acc[nt][2])*k0*r1;
            acc[nt][3] = pexp(acc[nt][3])*k1*r1;
        }
    } else {
        // leaf1 = exp(tr)*w_{2i}[k] -> Ls1
        #pragma unroll
        for (int nt = 0; nt < 8; nt++) {
            float k0 = ws1[nt*8+nc], k1 = ws1[nt*8+nc+1];
            *(__half2*)(Ls1 + m0*SMS + nt*8 + nc) =
                __floats2half2_rn(pexp(acc[nt][0])*k0, pexp(acc[nt][1])*k1);
            *(__half2*)(Ls1 + (m0+8)*SMS + nt*8 + nc) =
                __floats2half2_rn(pexp(acc[nt][2])*k0, pexp(acc[nt][3])*k1);
        }
        __syncthreads();   // GEMM1 reads done; Ls1 visible

        // ---- gather phase 2: E1[beam[rb]], E2[beam[rc]]^T ----
        for (int task = tid; task < 512; task += 128) {
            int j = task >> 3, q = task & 7;
            float4 v = ((const float4*)(E1 + (size_t)d_beam_idx[rb*BM + j]*RR))[q];
            __half2 h0 = __floats2half2_rn(v.x, v.y), h1 = __floats2half2_rn(v.z, v.w);
            *(uint2*)&E1s[j*ASTR + q*4] =
                make_uint2(*(uint32_t*)&h0, *(uint32_t*)&h1);
            float4 u = ((const float4*)(E2 + (size_t)d_beam_idx[rc*BM + j]*RR))[q];
            E2T[(4*q+0)*SMS + j] = __float2half_rn(u.x);
            E2T[(4*q+1)*SMS + j] = __float2half_rn(u.y);
            E2T[(4*q+2)*SMS + j] = __float2half_rn(u.z);
            E2T[(4*q+3)*SMS + j] = __float2half_rn(u.w);
        }
        __syncthreads();

        acc_zero(acc);
        mma64(aE1, aE2, acc, 2, ASTR);
        #pragma unroll
        for (int nt = 0; nt < 8; nt++) {
            float k0 = ws2[nt*8+nc], k1 = ws2[nt*8+nc+1];
            *(__half2*)(Ls2 + m0*SMS + nt*8 + nc) =
                __floats2half2_rn(pexp(acc[nt][0])*k0, pexp(acc[nt][1])*k1);
            *(__half2*)(Ls2 + (m0+8)*SMS + nt*8 + nc) =
                __floats2half2_rn(pexp(acc[nt][2])*k0, pexp(acc[nt][3])*k1);
        }
        __syncthreads();

        acc_zero(acc);
        mma64(aL1, aL2, acc, 4, SMS);       // node = leaf1 * leaf2
    }

    float mx = blockmax(acc, red);
    const float inv = __fdividef(1.0f, mx);
    store_frag(d_bufA + ((size_t)b*256 + i)*4096, acc, inv, 64);
    if (tid == 0) d_sA[b*256 + i] = logf(mx);
}

// ============================================================================
// K3: binary tree level (proven R7 structure, via shared helpers)
// ============================================================================
__global__ void __launch_bounds__(128) gemm_level(
    const __half* __restrict__ src, __half* __restrict__ dst,
    const float* __restrict__ ss, float* __restrict__ ds,
    int ndst, int sstride, int dstride)
{
    __shared__ __align__(16) __half As[64*SMS];
    __shared__ __align__(16) __half Bs[64*SMS];
    __shared__ float red[4];

    const int tid = threadIdx.x;
    const int b = blockIdx.x / ndst, i = blockIdx.x % ndst;
    const size_t s0 = ((size_t)b*sstride + 2*i) * 4096;

    const uint32_t aA = (uint32_t)__cvta_generic_to_shared(As);
    const uint32_t aB = (uint32_t)__cvta_generic_to_shared(Bs);
    #pragma unroll
    for (int c = 0; c < 4; c++) {
        int chunk = tid + c*128;
        int j = chunk >> 3, q = chunk & 7;
        asm volatile("cp.async.cg.shared.global [%0],[%1],16;\n"
            :: "r"(aA + (uint32_t)(j*SMS + q*8)*2), "l"(src + s0 + j*64 + q*8));
        asm volatile("cp.async.cg.shared.global [%0],[%1],16;\n"
            :: "r"(aB + (uint32_t)(j*SMS + q*8)*2), "l"(src + s0 + 4096 + j*64 + q*8));
    }
    asm volatile("cp.async.commit_group;\n");
    asm volatile("cp.async.wait_group 0;\n");
    __syncthreads();

    float acc[8][4];
    acc_zero(acc);
    mma64(aA, aB, acc, 4, SMS);

    float mx = blockmax(acc, red);
    const float inv = __fdividef(1.0f, mx);
    store_frag(dst + ((size_t)b*dstride + i)*4096, acc, inv, 64);
    if (tid == 0)
        ds[b*dstride + i] = ss[b*sstride + 2*i] + ss[b*sstride + 2*i + 1] + logf(mx);
}

// ============================================================================
// K3b: 4-ary level: dst[i] = norm(((s[4i]*s[4i+1])*s[4i+2])*s[4i+3])
// ============================================================================
__global__ void __launch_bounds__(128) gemm4_level(
    const __half* __restrict__ src, __half* __restrict__ dst,
    const float* __restrict__ ss, float* __restrict__ ds,
    int ndst, int sstride, int dstride)
{
    __shared__ __align__(16) __half As[64*SMS];
    __shared__ __align__(16) __half Bs0[64*SMS];
    __shared__ __align__(16) __half Bs1[64*SMS];
    __shared__ float red[4];

    const int tid = threadIdx.x;
    const int b = blockIdx.x / ndst, i = blockIdx.x % ndst;
    const size_t c0 = ((size_t)b*sstride + 4*i) * 4096;

    const uint32_t aA  = (uint32_t)__cvta_generic_to_shared(As);
    const uint32_t aB0 = (uint32_t)__cvta_generic_to_shared(Bs0);
    const uint32_t aB1 = (uint32_t)__cvta_generic_to_shared(Bs1);

    #pragma unroll
    for (int c = 0; c < 4; c++) {
        int chunk = tid + c*128;
        int j = chunk >> 3, q = chunk & 7;
        asm volatile("cp.async.cg.shared.global [%0],[%1],16;\n"
            :: "r"(aA  + (uint32_t)(j*SMS + q*8)*2), "l"(src + c0 + j*64 + q*8));
        asm volatile("cp.async.cg.shared.global [%0],[%1],16;\n"
            :: "r"(aB0 + (uint32_t)(j*SMS + q*8)*2), "l"(src + c0 + 4096 + j*64 + q*8));
    }
    asm volatile("cp.async.commit_group;\n");
    #pragma unroll
    for (int c = 0; c < 4; c++) {
        int chunk = tid + c*128;
        int j = chunk >> 3, q = chunk & 7;
        asm volatile("cp.async.cg.shared.global [%0],[%1],16;\n"
            :: "r"(aB1 + (uint32_t)(j*SMS + q*8)*2), "l"(src + c0 + 2*4096 + j*64 + q*8));
    }
    asm volatile("cp.async.commit_group;\n");
    asm volatile("cp.async.wait_group 1;\n");
    __syncthreads();

    float acc[8][4];
    float logcum = 0.f;

    acc_zero(acc);
    mma64(aA, aB0, acc, 4, SMS);
    float mx = blockmax(acc, red);          // barrier: all GEMM reads done
    logcum += logf(mx);
    // refill Bs0 with child 3 while we normalize
    #pragma unroll
    for (int c = 0; c < 4; c++) {
        int chunk = tid + c*128;
        int j = chunk >> 3, q = chunk & 7;
        asm volatile("cp.async.cg.shared.global [%0],[%1],16;\n"
            :: "r"(aB0 + (uint32_t)(j*SMS + q*8)*2), "l"(src + c0 + 3*4096 + j*64 + q*8));
    }
    asm volatile("cp.async.commit_group;\n");
    store_frag(As, acc, __fdividef(1.0f, mx), SMS);
    asm volatile("cp.async.wait_group 1;\n");   // Bs1 ready
    __syncthreads();

    acc_zero(acc);
    mma64(aA, aB1, acc, 4, SMS);
    mx = blockmax(acc, red);
    logcum += logf(mx);
    store_frag(As, acc, __fdividef(1.0f, mx), SMS);
    asm volatile("cp.async.wait_group 0;\n");   // Bs0 (child 3) ready
    __syncthreads();

    acc_zero(acc);
    mma64(aA, aB0, acc, 4, SMS);
    mx = blockmax(acc, red);
    store_frag(dst + ((size_t)b*dstride + i)*4096, acc, __fdividef(1.0f, mx), 64);
    if (tid == 0)
        ds[b*dstride + i] = ss[b*sstride + 4*i] + ss[b*sstride + 4*i + 1]
                          + ss[b*sstride + 4*i + 2] + ss[b*sstride + 4*i + 3]
                          + logcum + logf(mx);
}

// ============================================================================
// num partials: 64 blocks x 64 threads, one position each
// ============================================================================
__global__ void __launch_bounds__(64) numpart_kernel(
    const float* __restrict__ em, const void* __restrict__ tg,
    const float* __restrict__ E1, const float* __restrict__ E2)
{
    __shared__ float red2[2];
    const int blk = blockIdx.x, b = blk >> 3, p = blk & 7;
    const int t = p*64 + threadIdx.x;
    const int row = b*SS + t;
    const int cur = get_tgt(tg, row);
    float v = em[(size_t)row*V + cur];
    if (t > 0) {
        const int pv = get_tgt(tg, row-1);
        const float4* e1 = (const float4*)(E1 + (size_t)pv*RR);
        const float4* e2 = (const float4*)(E2 + (size_t)cur*RR);
        float d = 0.f;
        #pragma unroll
        for (int q = 0; q < 8; q++) {
            float4 a = e1[q], c = e2[q];
            d += a.x*c.x + a.y*c.y + a.z*c.z + a.w*c.w;
        }
        v += d;
    }
    #pragma unroll
    for (int o = 16; o; o >>= 1) v += __shfl_xor_sync(0xffffffffu, v, o);
    if ((threadIdx.x & 31) == 0) red2[threadIdx.x >> 5] = v;
    __syncthreads();
    if (threadIdx.x == 0) d_numpart[blk] = red2[0] + red2[1];
}

// ============================================================================
// den: den[b] = M + s_root + log(sum root entries); root in d_bufA
// ============================================================================
__global__ void __launch_bounds__(256) den_kernel()
{
    __shared__ float rbuf[8];
    const int tid = threadIdx.x, b = blockIdx.x;
    const int w = tid >> 5, l = tid & 31;

    const __half2* root = (const __half2*)(d_bufA + (size_t)b*256*4096);
    float s = 0.f;
    for (int i = tid; i < 2048; i += 256) {
        float2 f = __half22float2(root[i]);
        s += f.x + f.y;
    }
    #pragma unroll
    for (int o = 16; o; o >>= 1) s += __shfl_xor_sync(0xffffffffu, s, o);
    if (l == 0) rbuf[w] = s;
    __syncthreads();
    float S = 0.f;
    if (tid == 0) for (int i = 0; i < 8; i++) S += rbuf[i];
    __syncthreads();

    float mv = 0.f;
    for (int t = tid; t < SS; t += 256) mv += d_emref[b*SS + t];
    #pragma unroll
    for (int o = 16; o; o >>= 1) mv += __shfl_xor_sync(0xffffffffu, mv, o);
    if (l == 0) rbuf[w] = mv;
    __syncthreads();
    if (tid == 0) {
        float M = 0.f;
        for (int i = 0; i < 8; i++) M += rbuf[i];
        d_den[b] = M + d_sA[b] + logf(S);
    }
}

// ============================================================================
// epilogue
// ============================================================================
__global__ void out_kernel(float* __restrict__ out, int out_size)
{
    __shared__ float ll[BB];
    const int t = threadIdx.x;
    if (t < BB) {
        float n = 0.f;
        for (int p = 0; p < 8; p++) n += d_numpart[t*8 + p];
        ll[t] = n - d_den[t];
    }
    __syncthreads();
    if (t == 0) {
        float sum = 0.f;
        for (int i = 0; i < BB; i++) sum += ll[i];
        if (out_size > BB) {
            out[0] = sum;
            for (int i = 0; i < BB; i++) out[1+i] = ll[i];
        } else if (out_size == BB) {
            for (int i = 0; i < BB; i++) out[i] = ll[i];
        } else {
            out[0] = sum;
        }
    }
}

// ============================================================================
extern "C" void kernel_launch(void* const* d_in, const int* in_sizes, int n_in,
                              void* d_out, int out_size)
{
    const float* em = (const float*)d_in[0];
    const void*  tg = d_in[1];
    const float* E1 = (const float*)d_in[3];
    const float* E2 = (const float*)d_in[4];
    float* out = (float*)d_out;

    detect_kernel<<<1, 256>>>((const int*)tg);
    topk_kernel<<<ROWS, 256>>>(em, tg);
    numpart_kernel<<<64, 64>>>(em, tg, E1, E2);
    leaf_l0_kernel<<<BB*256, 128>>>(E1, E2);           // leaves + L0: 512 -> 256

    __half *bufA = nullptr, *bufB = nullptr;
    float  *sA = nullptr, *sB = nullptr;
    cudaGetSymbolAddress((void**)&bufA, d_bufA);
    cudaGetSymbolAddress((void**)&bufB, d_bufB);
    cudaGetSymbolAddress((void**)&sA, d_sA);
    cudaGetSymbolAddress((void**)&sB, d_sB);

    gemm_level <<<BB*128, 128>>>(bufA, bufB, sA, sB, 128, 256, 128); // 256->128
    gemm_level <<<BB* 64, 128>>>(bufB, bufA, sB, sA,  64, 128,  64); // 128->64
    gemm_level <<<BB* 32, 128>>>(bufA, bufB, sA, sB,  32,  64,  32); //  64->32
    gemm4_level<<<BB*  8, 128>>>(bufB, bufA, sB, sA,   8,  32,   8); //  32->8
    gemm4_level<<<BB*  2, 128>>>(bufA, bufB, sA, sB,   2,   8,   2); //   8->2
    gemm_level <<<BB*  1, 128>>>(bufB, bufA, sB, sA,   1,   2,   1); //   2->1

    den_kernel<<<BB, 256>>>();
    out_kernel<<<1, 32>>>(out, out_size);
}